// round 7
// baseline (speedup 1.0000x reference)
#include <cuda_runtime.h>
#include <cstdint>

#define NROI 1024
#define M_TOT (NROI * 196)          // 200704
#define KTOT  2304
#define WLSTRIDE (256 * KTOT)

// Device-global scratch (allocation-free per harness rules)
__device__ float g_buf0[M_TOT * 256];
__device__ float g_buf1[M_TOT * 256];
__device__ float g_wT[4 * 256 * KTOT];     // conv weights [layer][co][k], tf32
__device__ float g_wdT[4 * 256 * 256];     // deconv weights [parity][co][ci], tf32
__device__ float g_wmT[80 * 256];          // mask weights [cls][ci], tf32
__device__ float g_zbuf[4L * M_TOT * 256]; // deconv output, parity-major (822 MB)

// ---------------------------------------------------------------------------
__device__ __forceinline__ uint32_t smem_u32(const void* p) {
    uint32_t a;
    asm("{ .reg .u64 t; cvta.to.shared.u64 t, %1; cvt.u32.u64 %0, t; }"
        : "=r"(a) : "l"(p));
    return a;
}
__device__ __forceinline__ float tf32r(float x) {
    float o; asm("cvt.rna.tf32.f32 %0, %1;" : "=f"(o) : "f"(x)); return o;
}
__device__ __forceinline__ void cp16(uint32_t dst, const void* src, uint32_t bytes) {
    asm volatile("cp.async.cg.shared.global [%0], [%1], 16, %2;"
                 :: "r"(dst), "l"(src), "r"(bytes) : "memory");
}
__device__ __forceinline__ void mma_tf32(float c[4], const uint32_t a[4],
                                         const uint32_t b[2]) {
    asm volatile(
        "mma.sync.aligned.m16n8k8.row.col.f32.tf32.tf32.f32 "
        "{%0,%1,%2,%3}, {%4,%5,%6,%7}, {%8,%9}, {%0,%1,%2,%3};"
        : "+f"(c[0]), "+f"(c[1]), "+f"(c[2]), "+f"(c[3])
        : "r"(a[0]), "r"(a[1]), "r"(a[2]), "r"(a[3]), "r"(b[0]), "r"(b[1]));
}

// ---------------------------------------------------------------------------
// Prep kernels (unchanged)
// ---------------------------------------------------------------------------
__global__ __launch_bounds__(256)
void round_tf32_kernel(const float* __restrict__ in, float* __restrict__ out)
{
    int i = (blockIdx.x * 256 + threadIdx.x) * 4;
    float4 v = *(const float4*)(in + i);
    v.x = tf32r(v.x); v.y = tf32r(v.y); v.z = tf32r(v.z); v.w = tf32r(v.w);
    *(float4*)(out + i) = v;
}

__global__ __launch_bounds__(256)
void transpose_w(const float* __restrict__ Wc, float* __restrict__ wT)
{
    __shared__ float ts[32][33];
    const int l  = blockIdx.z;
    const int kq = blockIdx.y;
    const int ci0 = (blockIdx.x >> 3) * 32;
    const int co0 = (blockIdx.x & 7) * 32;
    const int tx = threadIdx.x & 31, ty = threadIdx.x >> 5;
#pragma unroll
    for (int i = ty; i < 32; i += 8)
        ts[i][tx] = tf32r(Wc[((l * 9 + kq) * 256 + ci0 + i) * 256 + co0 + tx]);
    __syncthreads();
#pragma unroll
    for (int i = ty; i < 32; i += 8)
        wT[(l * 256 + co0 + i) * KTOT + kq * 256 + ci0 + tx] = ts[tx][i];
}

__global__ __launch_bounds__(256)
void transpose_wd(const float* __restrict__ Wt, float* __restrict__ wdT)
{
    __shared__ float ts[32][33];
    const int ab  = blockIdx.z;
    const int ci0 = (blockIdx.x >> 3) * 32;
    const int co0 = (blockIdx.x & 7) * 32;
    const int tx = threadIdx.x & 31, ty = threadIdx.x >> 5;
    const float* src = Wt + (3 - ab) * 65536;
#pragma unroll
    for (int i = ty; i < 32; i += 8)
        ts[i][tx] = tf32r(src[(ci0 + i) * 256 + co0 + tx]);
    __syncthreads();
#pragma unroll
    for (int i = ty; i < 32; i += 8)
        wdT[ab * 65536 + (co0 + i) * 256 + ci0 + tx] = ts[tx][i];
}

__global__ __launch_bounds__(256)
void transpose_wm(const float* __restrict__ Wm, float* __restrict__ wmT)
{
    int i = blockIdx.x * 256 + threadIdx.x;
    if (i < 80 * 256) {
        int cls = i >> 8, ci = i & 255;
        wmT[i] = tf32r(Wm[ci * 80 + cls]);
    }
}

// ---------------------------------------------------------------------------
// Conv 3x3 SAME (256->256) + bias + ReLU via mma.sync tf32.
// NEW geometry: BM=128, BN=256 (full output channels, grid.y=1), BK=32,
// 512 threads = 16 warps (4M x 4N), warp tile 32x64, c[2][8][4].
// A traffic halved vs R6; same total warps/SM (16, one CTA).
// ---------------------------------------------------------------------------
#define APITCH 40
#define ASZ (128 * APITCH * 4)                   // 20480 B per A stage
#define BSZ (256 * APITCH * 4)                   // 40960 B per B stage
#define SMEM_CONV (2 * ASZ + 2 * BSZ + 1024)     // 123904 B

__global__ __launch_bounds__(512, 1)
void conv3x3_mma(const float* __restrict__ in,
                 const float* __restrict__ wT,    // [256][2304] tf32
                 const float* __restrict__ bias,
                 float* __restrict__ out)
{
    extern __shared__ float smem[];
    const uint32_t sb = smem_u32(smem);
    float* bias_s = smem + (2 * ASZ + 2 * BSZ) / 4;

    const int t = threadIdx.x, wid = t >> 5, lane = t & 31;
    const int g = lane >> 2, tig = lane & 3;
    const int m0 = blockIdx.x * 128;
    const int warpM = (wid & 3) * 32;
    const int warpN = (wid >> 2) * 64;

    if (t < 64) ((float4*)bias_s)[t] = ((const float4*)bias)[t];

    // A: 128 rows x 32k = 1024 16B-chunks -> 2 per thread
    int ahh[2], aww[2]; long abase[2];
    uint32_t adst[2];
#pragma unroll
    for (int s = 0; s < 2; ++s) {
        int id  = t + s * 512;
        int row = id >> 3;
        int cq4 = (id & 7) * 4;
        int m = m0 + row;
        int n = m / 196;
        int pp = m - n * 196;
        int hh = pp / 14;
        ahh[s] = hh; aww[s] = pp - hh * 14;
        abase[s] = (long)n * 50176 + cq4;
        adst[s] = sb + (row * APITCH + cq4) * 4;
    }
    // B: 256 rows x 32k = 2048 chunks -> 4 per thread
    uint32_t bdst[4];
    const float* bsrc[4];
#pragma unroll
    for (int s = 0; s < 4; ++s) {
        int id  = t + s * 512;
        int row = id >> 3;
        int cq4 = (id & 7) * 4;
        bsrc[s] = wT + (long)row * KTOT + cq4;
        bdst[s] = sb + 2 * ASZ + (row * APITCH + cq4) * 4;
    }

    float c[2][8][4];
#pragma unroll
    for (int i = 0; i < 2; ++i)
#pragma unroll
        for (int j = 0; j < 8; ++j)
#pragma unroll
            for (int q = 0; q < 4; ++q) c[i][j][q] = 0.f;

    auto load_tile = [&](int kt, int p) {
        const int kq = kt >> 3, ci0 = (kt & 7) << 5;
        const int kh = kq / 3, kw = kq - kh * 3;
#pragma unroll
        for (int s = 0; s < 2; ++s) {
            int ih = ahh[s] + kh - 1, iw = aww[s] + kw - 1;
            bool ok = ((unsigned)ih < 14u) & ((unsigned)iw < 14u);
            int ihc = ok ? ih : 0, iwc = ok ? iw : 0;
            cp16(adst[s] + p * ASZ, in + abase[s] + (ihc * 14 + iwc) * 256 + ci0,
                 ok ? 16u : 0u);
        }
#pragma unroll
        for (int s = 0; s < 4; ++s)
            cp16(bdst[s] + p * BSZ, bsrc[s] + kt * 32, 16u);
        asm volatile("cp.async.commit_group;" ::: "memory");
    };

    load_tile(0, 0);

    for (int kt = 0; kt < 72; ++kt) {
        const int p = kt & 1;
        if (kt < 71) {
            load_tile(kt + 1, p ^ 1);
            asm volatile("cp.async.wait_group 1;" ::: "memory");
        } else {
            asm volatile("cp.async.wait_group 0;" ::: "memory");
        }
        __syncthreads();

        const float* As = smem + p * (ASZ / 4);
        const float* Bs = smem + (2 * ASZ + p * BSZ) / 4;
#pragma unroll
        for (int ks = 0; ks < 4; ++ks) {
            const int kb = ks * 8 + tig * 2;
            uint32_t a[2][4], bf[8][2];
#pragma unroll
            for (int i = 0; i < 2; ++i) {
                float2 v0 = *(const float2*)&As[(warpM + i * 16 + g) * APITCH + kb];
                float2 v1 = *(const float2*)&As[(warpM + i * 16 + g + 8) * APITCH + kb];
                a[i][0] = __float_as_uint(v0.x); a[i][2] = __float_as_uint(v0.y);
                a[i][1] = __float_as_uint(v1.x); a[i][3] = __float_as_uint(v1.y);
            }
#pragma unroll
            for (int j = 0; j < 8; ++j) {
                float2 v = *(const float2*)&Bs[(warpN + j * 8 + g) * APITCH + kb];
                bf[j][0] = __float_as_uint(v.x); bf[j][1] = __float_as_uint(v.y);
            }
#pragma unroll
            for (int i = 0; i < 2; ++i)
#pragma unroll
                for (int j = 0; j < 8; ++j)
                    mma_tf32(c[i][j], a[i], bf[j]);
        }
        __syncthreads();
    }

    // epilogue: bias + relu + tf32 round
#pragma unroll
    for (int j = 0; j < 8; ++j) {
        const int col = warpN + j * 8 + tig * 2;
        const float b0 = bias_s[col], b1 = bias_s[col + 1];
#pragma unroll
        for (int i = 0; i < 2; ++i) {
            long r0 = m0 + warpM + i * 16 + g;
            float2 o0, o1;
            o0.x = tf32r(fmaxf(c[i][j][0] + b0, 0.f));
            o0.y = tf32r(fmaxf(c[i][j][1] + b1, 0.f));
            o1.x = tf32r(fmaxf(c[i][j][2] + b0, 0.f));
            o1.y = tf32r(fmaxf(c[i][j][3] + b1, 0.f));
            *(float2*)&out[(r0 << 8) + col]       = o0;
            *(float2*)&out[((r0 + 8) << 8) + col] = o1;
        }
    }
}

// ---------------------------------------------------------------------------
// D1: deconv GEMM per parity (unchanged from R6 pass)
// ---------------------------------------------------------------------------
#define DTILE_BYTES (128 * APITCH * 4)           // 20480
#define SMEM_DCONV (4 * DTILE_BYTES + 1024)      // 82944

__global__ __launch_bounds__(256, 2)
void deconv_gemm(const float* __restrict__ y,
                 const float* __restrict__ wdT,
                 const float* __restrict__ bt,
                 float* __restrict__ z)
{
    extern __shared__ float smem[];
    const uint32_t sb = smem_u32(smem);
    float* bias_s = smem + 4 * 128 * APITCH;

    const int t = threadIdx.x, wid = t >> 5, lane = t & 31;
    const int g = lane >> 2, tig = lane & 3;
    const int m0 = blockIdx.x * 128;
    const int n0 = blockIdx.y * 128;
    const int ab = blockIdx.z;
    const int warpM = (wid & 1) * 64;
    const int warpN = (wid >> 1) * 32;

    if (t < 32) ((float4*)bias_s)[t] = ((const float4*)(bt + n0))[t];

    const int cq4 = (t & 7) * 4;
    uint32_t adst[4], bdst[4];
    const float* asrc[4];
    const float* bsrc[4];
#pragma unroll
    for (int s = 0; s < 4; ++s) {
        int row = (t >> 3) + s * 32;
        asrc[s] = y + (long)(m0 + row) * 256 + cq4;
        adst[s] = sb + (row * APITCH + cq4) * 4;
        bsrc[s] = wdT + ab * 65536 + (n0 + row) * 256 + cq4;
        bdst[s] = sb + 2 * DTILE_BYTES + (row * APITCH + cq4) * 4;
    }

    float c[4][4][4];
#pragma unroll
    for (int i = 0; i < 4; ++i)
#pragma unroll
        for (int j = 0; j < 4; ++j)
#pragma unroll
            for (int q = 0; q < 4; ++q) c[i][j][q] = 0.f;

    auto load_tile = [&](int kt, int p) {
        const uint32_t off = p * DTILE_BYTES;
#pragma unroll
        for (int s = 0; s < 4; ++s) cp16(adst[s] + off, asrc[s] + kt * 32, 16u);
#pragma unroll
        for (int s = 0; s < 4; ++s) cp16(bdst[s] + off, bsrc[s] + kt * 32, 16u);
        asm volatile("cp.async.commit_group;" ::: "memory");
    };

    load_tile(0, 0);

    for (int kt = 0; kt < 8; ++kt) {
        const int p = kt & 1;
        if (kt < 7) {
            load_tile(kt + 1, p ^ 1);
            asm volatile("cp.async.wait_group 1;" ::: "memory");
        } else {
            asm volatile("cp.async.wait_group 0;" ::: "memory");
        }
        __syncthreads();

        const float* As = smem + p * (DTILE_BYTES / 4);
        const float* Bs = smem + (2 + p) * (DTILE_BYTES / 4);
#pragma unroll
        for (int ks = 0; ks < 4; ++ks) {
            const int kb = ks * 8 + tig * 2;
            uint32_t a[4][4], bf[4][2];
#pragma unroll
            for (int i = 0; i < 4; ++i) {
                float2 v0 = *(const float2*)&As[(warpM + i * 16 + g) * APITCH + kb];
                float2 v1 = *(const float2*)&As[(warpM + i * 16 + g + 8) * APITCH + kb];
                a[i][0] = __float_as_uint(v0.x); a[i][2] = __float_as_uint(v0.y);
                a[i][1] = __float_as_uint(v1.x); a[i][3] = __float_as_uint(v1.y);
            }
#pragma unroll
            for (int j = 0; j < 4; ++j) {
                float2 v = *(const float2*)&Bs[(warpN + j * 8 + g) * APITCH + kb];
                bf[j][0] = __float_as_uint(v.x); bf[j][1] = __float_as_uint(v.y);
            }
#pragma unroll
            for (int i = 0; i < 4; ++i)
#pragma unroll
                for (int j = 0; j < 4; ++j)
                    mma_tf32(c[i][j], a[i], bf[j]);
        }
        __syncthreads();
    }

    float* zout = z + (long)ab * M_TOT * 256;
#pragma unroll
    for (int j = 0; j < 4; ++j) {
        const int col = warpN + j * 8 + tig * 2;
        const float b0 = bias_s[col], b1 = bias_s[col + 1];
#pragma unroll
        for (int i = 0; i < 4; ++i) {
            long r0 = m0 + warpM + i * 16 + g;
            float2 o0, o1;
            o0.x = tf32r(fmaxf(c[i][j][0] + b0, 0.f));
            o0.y = tf32r(fmaxf(c[i][j][1] + b1, 0.f));
            o1.x = tf32r(fmaxf(c[i][j][2] + b0, 0.f));
            o1.y = tf32r(fmaxf(c[i][j][3] + b1, 0.f));
            *(float2*)&zout[(r0 << 8) + n0 + col]       = o0;
            *(float2*)&zout[((r0 + 8) << 8) + n0 + col] = o1;
        }
    }
}

// ---------------------------------------------------------------------------
// D2: mask GEMM (unchanged from R6 pass)
// ---------------------------------------------------------------------------
#define D2_ASIZE (128 * APITCH)     // 5120 floats
#define D2_BSIZE (80 * APITCH)      // 3200 floats
#define SMEM_D2  ((2 * D2_ASIZE + 2 * D2_BSIZE) * 4)   // 66560 B

__global__ __launch_bounds__(256, 2)
void mask_gemm(const float* __restrict__ z,
               const float* __restrict__ wmT,
               const float* __restrict__ bm,
               float* __restrict__ out)
{
    extern __shared__ float smem[];
    const uint32_t sb = smem_u32(smem);
    const int t = threadIdx.x, wid = t >> 5, lane = t & 31;
    const int g = lane >> 2, tig = lane & 3;
    const long m0 = (long)blockIdx.x * 128;
    const int ab = (int)(m0 / M_TOT);
    const int aa = ab >> 1, bb = ab & 1;
    const int pix0 = (int)(m0 - (long)ab * M_TOT);

    const int cq4 = (t & 7) * 4;
    uint32_t adst[4]; const float* asrc[4];
#pragma unroll
    for (int s = 0; s < 4; ++s) {
        int row = (t >> 3) + s * 32;
        asrc[s] = z + (m0 + row) * 256 + cq4;
        adst[s] = sb + (row * APITCH + cq4) * 4;
    }

    float c[10][4];
#pragma unroll
    for (int j = 0; j < 10; ++j)
#pragma unroll
        for (int q = 0; q < 4; ++q) c[j][q] = 0.f;

    auto load_tile = [&](int kt, int p) {
#pragma unroll
        for (int s = 0; s < 4; ++s)
            cp16(adst[s] + p * (D2_ASIZE * 4), asrc[s] + kt * 32, 16u);
        for (int ch = t; ch < 640; ch += 256) {
            int row = ch >> 3, k4 = (ch & 7) * 4;
            cp16(sb + (2 * D2_ASIZE + p * D2_BSIZE + row * APITCH + k4) * 4,
                 wmT + row * 256 + kt * 32 + k4, 16u);
        }
        asm volatile("cp.async.commit_group;" ::: "memory");
    };

    load_tile(0, 0);

    for (int kt = 0; kt < 8; ++kt) {
        const int p = kt & 1;
        if (kt < 7) {
            load_tile(kt + 1, p ^ 1);
            asm volatile("cp.async.wait_group 1;" ::: "memory");
        } else {
            asm volatile("cp.async.wait_group 0;" ::: "memory");
        }
        __syncthreads();

        const float* As = smem + p * D2_ASIZE;
        const float* Bs = smem + 2 * D2_ASIZE + p * D2_BSIZE;
#pragma unroll
        for (int ks = 0; ks < 4; ++ks) {
            const int kb = ks * 8 + tig * 2;
            uint32_t a[4];
            float2 v0 = *(const float2*)&As[(wid * 16 + g) * APITCH + kb];
            float2 v1 = *(const float2*)&As[(wid * 16 + g + 8) * APITCH + kb];
            a[0] = __float_as_uint(v0.x); a[2] = __float_as_uint(v0.y);
            a[1] = __float_as_uint(v1.x); a[3] = __float_as_uint(v1.y);
#pragma unroll
            for (int j = 0; j < 10; ++j) {
                float2 v = *(const float2*)&Bs[(j * 8 + g) * APITCH + kb];
                uint32_t bf[2] = {__float_as_uint(v.x), __float_as_uint(v.y)};
                mma_tf32(c[j], a, bf);
            }
        }
        __syncthreads();
    }

    float bmv[10][2];
#pragma unroll
    for (int j = 0; j < 10; ++j) {
        int col = j * 8 + tig * 2;
        bmv[j][0] = bm[col]; bmv[j][1] = bm[col + 1];
    }

    int pixA = pix0 + wid * 16 + g;
    int pixB = pixA + 8;
    int nA = pixA / 196, pA = pixA - nA * 196, iiA = pA / 14, jjA = pA - iiA * 14;
    int nB = pixB / 196, pB = pixB - nB * 196, iiB = pB / 14, jjB = pB - iiB * 14;
    float* opA = out + ((long)(nA * 28 + iiA * 2 + aa) * 28 + jjA * 2 + bb) * 80;
    float* opB = out + ((long)(nB * 28 + iiB * 2 + aa) * 28 + jjB * 2 + bb) * 80;

#pragma unroll
    for (int j = 0; j < 10; ++j) {
        int col = j * 8 + tig * 2;
        float2 oA = make_float2(c[j][0] + bmv[j][0], c[j][1] + bmv[j][1]);
        float2 oB = make_float2(c[j][2] + bmv[j][0], c[j][3] + bmv[j][1]);
        *(float2*)&opA[col] = oA;
        *(float2*)&opB[col] = oB;
    }
}

// ---------------------------------------------------------------------------
extern "C" void kernel_launch(void* const* d_in, const int* in_sizes, int n_in,
                              void* d_out, int out_size)
{
    const float* x  = (const float*)d_in[0];
    const float* Wc = (const float*)d_in[1];
    const float* bc = (const float*)d_in[2];
    const float* Wt = (const float*)d_in[3];
    const float* bt = (const float*)d_in[4];
    const float* Wm = (const float*)d_in[5];
    const float* bm = (const float*)d_in[6];
    float* out = (float*)d_out;

    float *b0, *b1, *wT, *wdT, *wmT, *zbuf;
    cudaGetSymbolAddress((void**)&b0,  g_buf0);
    cudaGetSymbolAddress((void**)&b1,  g_buf1);
    cudaGetSymbolAddress((void**)&wT,  g_wT);
    cudaGetSymbolAddress((void**)&wdT, g_wdT);
    cudaGetSymbolAddress((void**)&wmT, g_wmT);
    cudaGetSymbolAddress((void**)&zbuf, g_zbuf);

    cudaFuncSetAttribute(conv3x3_mma,
                         cudaFuncAttributeMaxDynamicSharedMemorySize, SMEM_CONV);
    cudaFuncSetAttribute(deconv_gemm,
                         cudaFuncAttributeMaxDynamicSharedMemorySize, SMEM_DCONV);
    cudaFuncSetAttribute(mask_gemm,
                         cudaFuncAttributeMaxDynamicSharedMemorySize, SMEM_D2);

    // prep
    round_tf32_kernel<<<(M_TOT * 256) / (256 * 4), 256>>>(x, b0);
    transpose_w<<<dim3(64, 9, 4), 256>>>(Wc, wT);
    transpose_wd<<<dim3(64, 1, 4), 256>>>(Wt, wdT);
    transpose_wm<<<80, 256>>>(Wm, wmT);

    // conv chain: BM=128, BN=256, 512 threads
    conv3x3_mma<<<1568, 512, SMEM_CONV>>>(b0, wT + 0L * WLSTRIDE, bc + 0,   b1);
    conv3x3_mma<<<1568, 512, SMEM_CONV>>>(b1, wT + 1L * WLSTRIDE, bc + 256, b0);
    conv3x3_mma<<<1568, 512, SMEM_CONV>>>(b0, wT + 2L * WLSTRIDE, bc + 512, b1);
    conv3x3_mma<<<1568, 512, SMEM_CONV>>>(b1, wT + 3L * WLSTRIDE, bc + 768, b0);

    // deconv (per parity) + mask
    deconv_gemm<<<dim3(1568, 2, 4), 256, SMEM_DCONV>>>(b0, wdT, bt, zbuf);
    mask_gemm<<<4 * M_TOT / 128, 256, SMEM_D2>>>(zbuf, wmT, bm, out);
}

// round 11
// speedup vs baseline: 1.7800x; 1.7800x over previous
// ROIMaskHead fp16 tensor-core pipeline, v3 (content-hash bump of R8/R9 design).
// conv3x3 x4 -> deconv(2x2,s2) -> 1x1 mask, all via mma.sync.m16n8k16.f16,
// ldmatrix.x4 fragment loads, cp.async double-buffered tiles, 2 CTAs/SM.
#include <cuda_runtime.h>
#include <cuda_fp16.h>
#include <cstdint>

#define NROI 1024
#define M_TOT (NROI * 196)          // 200704
#define KTOT  2304
#define WLSTRIDE (256 * KTOT)

// Device-global scratch (allocation-free per harness rules)
__device__ __half g_h0[M_TOT * 256];
__device__ __half g_h1[M_TOT * 256];
__device__ __half g_wTh[4 * 256 * KTOT];     // conv W [layer][co][k]
__device__ __half g_wdTh[4 * 256 * 256];     // deconv W [parity][co][ci]
__device__ __half g_wmTh[80 * 256];          // mask W [cls][ci]
__device__ __half g_zh[4L * M_TOT * 256];    // deconv out, parity-major

// ---------------------------------------------------------------------------
__device__ __forceinline__ uint32_t smem_u32(const void* p) {
    uint32_t a;
    asm("{ .reg .u64 t; cvta.to.shared.u64 t, %1; cvt.u32.u64 %0, t; }"
        : "=r"(a) : "l"(p));
    return a;
}
__device__ __forceinline__ void cp16(uint32_t dst, const void* src, uint32_t bytes) {
    asm volatile("cp.async.cg.shared.global [%0], [%1], 16, %2;"
                 :: "r"(dst), "l"(src), "r"(bytes) : "memory");
}
#define LDSM4(r0, r1, r2, r3, addr) \
    asm volatile("ldmatrix.sync.aligned.m8n8.x4.shared.b16 {%0,%1,%2,%3}, [%4];" \
                 : "=r"(r0), "=r"(r1), "=r"(r2), "=r"(r3) : "r"(addr))

__device__ __forceinline__ void mma_f16(float c[4], const uint32_t a[4],
                                        uint32_t b0, uint32_t b1) {
    asm volatile(
        "mma.sync.aligned.m16n8k16.row.col.f32.f16.f16.f32 "
        "{%0,%1,%2,%3}, {%4,%5,%6,%7}, {%8,%9}, {%0,%1,%2,%3};"
        : "+f"(c[0]), "+f"(c[1]), "+f"(c[2]), "+f"(c[3])
        : "r"(a[0]), "r"(a[1]), "r"(a[2]), "r"(a[3]), "r"(b0), "r"(b1));
}

// ---------------------------------------------------------------------------
// Prep kernels
// ---------------------------------------------------------------------------
__global__ __launch_bounds__(256)
void f2h_fp16(const float* __restrict__ in, __half* __restrict__ out)
{
    long i = (long)(blockIdx.x * 256 + threadIdx.x) * 8;
    float4 v0 = *(const float4*)(in + i);
    float4 v1 = *(const float4*)(in + i + 4);
    __half2 h[4];
    h[0] = __floats2half2_rn(v0.x, v0.y);
    h[1] = __floats2half2_rn(v0.z, v0.w);
    h[2] = __floats2half2_rn(v1.x, v1.y);
    h[3] = __floats2half2_rn(v1.z, v1.w);
    *(uint4*)(out + i) = *(uint4*)h;
}

__global__ __launch_bounds__(256)
void transpose_w_fp16(const float* __restrict__ Wc, __half* __restrict__ wTh)
{
    __shared__ float ts[32][33];
    const int l  = blockIdx.z;
    const int kq = blockIdx.y;
    const int ci0 = (blockIdx.x >> 3) * 32;
    const int co0 = (blockIdx.x & 7) * 32;
    const int tx = threadIdx.x & 31, ty = threadIdx.x >> 5;
#pragma unroll
    for (int i = ty; i < 32; i += 8)
        ts[i][tx] = Wc[((l * 9 + kq) * 256 + ci0 + i) * 256 + co0 + tx];
    __syncthreads();
#pragma unroll
    for (int i = ty; i < 32; i += 8)
        wTh[(long)(l * 256 + co0 + i) * KTOT + kq * 256 + ci0 + tx] =
            __float2half_rn(ts[tx][i]);
}

__global__ __launch_bounds__(256)
void transpose_wd_fp16(const float* __restrict__ Wt, __half* __restrict__ wdTh)
{
    __shared__ float ts[32][33];
    const int ab  = blockIdx.z;
    const int ci0 = (blockIdx.x >> 3) * 32;
    const int co0 = (blockIdx.x & 7) * 32;
    const int tx = threadIdx.x & 31, ty = threadIdx.x >> 5;
    const float* src = Wt + (3 - ab) * 65536;   // Wt[1-a][1-b] (proven in R1)
#pragma unroll
    for (int i = ty; i < 32; i += 8)
        ts[i][tx] = src[(ci0 + i) * 256 + co0 + tx];
    __syncthreads();
#pragma unroll
    for (int i = ty; i < 32; i += 8)
        wdTh[ab * 65536 + (co0 + i) * 256 + ci0 + tx] = __float2half_rn(ts[tx][i]);
}

__global__ __launch_bounds__(256)
void transpose_wm_fp16(const float* __restrict__ Wm, __half* __restrict__ wmTh)
{
    int i = blockIdx.x * 256 + threadIdx.x;
    if (i < 80 * 256) {
        int cls = i >> 8, ci = i & 255;
        wmTh[i] = __float2half_rn(Wm[ci * 80 + cls]);
    }
}

// ---------------------------------------------------------------------------
// Conv 3x3 SAME (256->256) + bias + ReLU, fp16 mma.m16n8k16.
// BM=128 BN=128 BK=32, 256 thr, 8 warps (2M x 4N), warp tile 64x32.
// Smem rows: 40 halves (80 B) pitch -> ldmatrix phase-conflict-free.
// ---------------------------------------------------------------------------
#define HSTAGE (128 * 40 * 2)                // 10240 B per tile stage
#define SMEM_CONVH (4 * HSTAGE + 1024)       // A(2) + B(2) + bias

__global__ __launch_bounds__(256, 2)
void conv3x3_fp16(const __half* __restrict__ in,
                  const __half* __restrict__ wTh,
                  const float* __restrict__ bias,
                  __half* __restrict__ out)
{
    extern __shared__ char smem[];
    const uint32_t sb = smem_u32(smem);
    float* bias_s = (float*)(smem + 4 * HSTAGE);

    const int t = threadIdx.x, wid = t >> 5, lane = t & 31;
    const int m0 = blockIdx.x * 128;
    const int n0 = blockIdx.y * 128;
    const int warpM = (wid & 1) * 64;
    const int warpN = (wid >> 1) * 32;

    if (t < 32) ((float4*)bias_s)[t] = ((const float4*)(bias + n0))[t];

    // load mapping: 2 A + 2 B 16B-chunks per thread (row=64B -> 4 chunks)
    int ahh[2], aww[2]; long abase[2];
    uint32_t adst[2], bdst[2];
    const __half* bsrc[2];
#pragma unroll
    for (int s = 0; s < 2; ++s) {
        int id  = t + s * 256;
        int row = id >> 2;
        int cq  = id & 3;
        int m = m0 + row;
        int n = m / 196;
        int pp = m - n * 196;
        int hh = pp / 14;
        ahh[s] = hh; aww[s] = pp - hh * 14;
        abase[s] = (long)n * 50176 + cq * 8;
        adst[s] = sb + row * 80 + cq * 16;
        bsrc[s] = wTh + (long)(n0 + row) * KTOT + cq * 8;
        bdst[s] = sb + 2 * HSTAGE + row * 80 + cq * 16;
    }

    float c[4][4][4];
#pragma unroll
    for (int i = 0; i < 4; ++i)
#pragma unroll
        for (int j = 0; j < 4; ++j)
#pragma unroll
            for (int q = 0; q < 4; ++q) c[i][j][q] = 0.f;

    auto load_tile = [&](int kt, int p) {
        const int kq = kt >> 3, ci0 = (kt & 7) << 5;
        const int kh = kq / 3, kw = kq - kh * 3;
#pragma unroll
        for (int s = 0; s < 2; ++s) {
            int ih = ahh[s] + kh - 1, iw = aww[s] + kw - 1;
            bool ok = ((unsigned)ih < 14u) & ((unsigned)iw < 14u);
            int ihc = ok ? ih : 0, iwc = ok ? iw : 0;
            cp16(adst[s] + p * HSTAGE, in + abase[s] + (ihc * 14 + iwc) * 256 + ci0,
                 ok ? 16u : 0u);
        }
#pragma unroll
        for (int s = 0; s < 2; ++s)
            cp16(bdst[s] + p * HSTAGE, bsrc[s] + kt * 32, 16u);
        asm volatile("cp.async.commit_group;" ::: "memory");
    };

    // ldmatrix lane addressing
    const int lr = (lane & 7) + ((lane >> 3) & 1) * 8;   // row within 16
    const int lk = (lane >> 4) * 8;                      // k col 0/8

    load_tile(0, 0);

    for (int kt = 0; kt < 72; ++kt) {
        const int p = kt & 1;
        if (kt < 71) {
            load_tile(kt + 1, p ^ 1);
            asm volatile("cp.async.wait_group 1;" ::: "memory");
        } else {
            asm volatile("cp.async.wait_group 0;" ::: "memory");
        }
        __syncthreads();

        const uint32_t Ab = sb + p * HSTAGE;
        const uint32_t Bb = sb + 2 * HSTAGE + p * HSTAGE;
#pragma unroll
        for (int ks = 0; ks < 2; ++ks) {
            const int kc = ks * 16 + lk;
            uint32_t a[4][4], bq[2][4];
#pragma unroll
            for (int i = 0; i < 4; ++i)
                LDSM4(a[i][0], a[i][1], a[i][2], a[i][3],
                      Ab + (warpM + i * 16 + lr) * 80 + kc * 2);
#pragma unroll
            for (int j2 = 0; j2 < 2; ++j2)
                LDSM4(bq[j2][0], bq[j2][1], bq[j2][2], bq[j2][3],
                      Bb + (warpN + j2 * 16 + lr) * 80 + kc * 2);
#pragma unroll
            for (int i = 0; i < 4; ++i)
#pragma unroll
                for (int j = 0; j < 4; ++j) {
                    const int j2 = j >> 1, hi = j & 1;
                    mma_f16(c[i][j], a[i], bq[j2][hi], bq[j2][hi + 2]);
                }
        }
        __syncthreads();
    }

    // epilogue: bias + relu -> half2
#pragma unroll
    for (int j = 0; j < 4; ++j) {
        const int col = warpN + j * 8 + (lane & 3) * 2;
        const float b0 = bias_s[col], b1 = bias_s[col + 1];
#pragma unroll
        for (int i = 0; i < 4; ++i) {
            long r0 = m0 + warpM + i * 16 + (lane >> 2);
            __half2 h0 = __floats2half2_rn(fmaxf(c[i][j][0] + b0, 0.f),
                                           fmaxf(c[i][j][1] + b1, 0.f));
            __half2 h1 = __floats2half2_rn(fmaxf(c[i][j][2] + b0, 0.f),
                                           fmaxf(c[i][j][3] + b1, 0.f));
            *(__half2*)&out[(r0 << 8) + n0 + col]       = h0;
            *(__half2*)&out[((r0 + 8) << 8) + n0 + col] = h1;
        }
    }
}

// ---------------------------------------------------------------------------
// D1: deconv GEMM per parity, fp16 (structure = conv3x3_fp16, K=256 dense)
// ---------------------------------------------------------------------------
__global__ __launch_bounds__(256, 2)
void deconv_fp16(const __half* __restrict__ y,
                 const __half* __restrict__ wdTh,
                 const float* __restrict__ bt,
                 __half* __restrict__ z)
{
    extern __shared__ char smem[];
    const uint32_t sb = smem_u32(smem);
    float* bias_s = (float*)(smem + 4 * HSTAGE);

    const int t = threadIdx.x, wid = t >> 5, lane = t & 31;
    const int m0 = blockIdx.x * 128;
    const int n0 = blockIdx.y * 128;
    const int ab = blockIdx.z;
    const int warpM = (wid & 1) * 64;
    const int warpN = (wid >> 1) * 32;

    if (t < 32) ((float4*)bias_s)[t] = ((const float4*)(bt + n0))[t];

    uint32_t adst[2], bdst[2];
    const __half* asrc[2];
    const __half* bsrc[2];
#pragma unroll
    for (int s = 0; s < 2; ++s) {
        int id  = t + s * 256;
        int row = id >> 2;
        int cq  = id & 3;
        asrc[s] = y + (long)(m0 + row) * 256 + cq * 8;
        adst[s] = sb + row * 80 + cq * 16;
        bsrc[s] = wdTh + ab * 65536 + (n0 + row) * 256 + cq * 8;
        bdst[s] = sb + 2 * HSTAGE + row * 80 + cq * 16;
    }

    float c[4][4][4];
#pragma unroll
    for (int i = 0; i < 4; ++i)
#pragma unroll
        for (int j = 0; j < 4; ++j)
#pragma unroll
            for (int q = 0; q < 4; ++q) c[i][j][q] = 0.f;

    auto load_tile = [&](int kt, int p) {
#pragma unroll
        for (int s = 0; s < 2; ++s) cp16(adst[s] + p * HSTAGE, asrc[s] + kt * 32, 16u);
#pragma unroll
        for (int s = 0; s < 2; ++s) cp16(bdst[s] + p * HSTAGE, bsrc[s] + kt * 32, 16u);
        asm volatile("cp.async.commit_group;" ::: "memory");
    };

    const int lr = (lane & 7) + ((lane >> 3) & 1) * 8;
    const int lk = (lane >> 4) * 8;

    load_tile(0, 0);

    for (int kt = 0; kt < 8; ++kt) {
        const int p = kt & 1;
        if (kt < 7) {
            load_tile(kt + 1, p ^ 1);
            asm volatile("cp.async.wait_group 1;" ::: "memory");
        } else {
            asm volatile("cp.async.wait_group 0;" ::: "memory");
        }
        __syncthreads();

        const uint32_t Ab = sb + p * HSTAGE;
        const uint32_t Bb = sb + 2 * HSTAGE + p * HSTAGE;
#pragma unroll
        for (int ks = 0; ks < 2; ++ks) {
            const int kc = ks * 16 + lk;
            uint32_t a[4][4], bq[2][4];
#pragma unroll
            for (int i = 0; i < 4; ++i)
                LDSM4(a[i][0], a[i][1], a[i][2], a[i][3],
                      Ab + (warpM + i * 16 + lr) * 80 + kc * 2);
#pragma unroll
            for (int j2 = 0; j2 < 2; ++j2)
                LDSM4(bq[j2][0], bq[j2][1], bq[j2][2], bq[j2][3],
                      Bb + (warpN + j2 * 16 + lr) * 80 + kc * 2);
#pragma unroll
            for (int i = 0; i < 4; ++i)
#pragma unroll
                for (int j = 0; j < 4; ++j) {
                    const int j2 = j >> 1, hi = j & 1;
                    mma_f16(c[i][j], a[i], bq[j2][hi], bq[j2][hi + 2]);
                }
        }
        __syncthreads();
    }

    __half* zout = z + (long)ab * M_TOT * 256;
#pragma unroll
    for (int j = 0; j < 4; ++j) {
        const int col = warpN + j * 8 + (lane & 3) * 2;
        const float b0 = bias_s[col], b1 = bias_s[col + 1];
#pragma unroll
        for (int i = 0; i < 4; ++i) {
            long r0 = m0 + warpM + i * 16 + (lane >> 2);
            __half2 h0 = __floats2half2_rn(fmaxf(c[i][j][0] + b0, 0.f),
                                           fmaxf(c[i][j][1] + b1, 0.f));
            __half2 h1 = __floats2half2_rn(fmaxf(c[i][j][2] + b0, 0.f),
                                           fmaxf(c[i][j][3] + b1, 0.f));
            *(__half2*)&zout[(r0 << 8) + n0 + col]       = h0;
            *(__half2*)&zout[((r0 + 8) << 8) + n0 + col] = h1;
        }
    }
}

// ---------------------------------------------------------------------------
// D2: mask GEMM fp16: out = z @ WmT^T + bm. M=802816, N=80, K=256.
// 8 warps, each 16 rows x 80 cols (10 n8 tiles), BK=32 double-buffered.
// ---------------------------------------------------------------------------
#define MB_STAGE (80 * 40 * 2)                   // 6400 B
#define SMEM_MASK (2 * HSTAGE + 2 * MB_STAGE)    // 33280 B

__global__ __launch_bounds__(256, 2)
void mask_fp16(const __half* __restrict__ z,
               const __half* __restrict__ wmTh,
               const float* __restrict__ bm,
               float* __restrict__ out)
{
    extern __shared__ char smem[];
    const uint32_t sb = smem_u32(smem);
    const int t = threadIdx.x, wid = t >> 5, lane = t & 31;
    const long m0 = (long)blockIdx.x * 128;
    const int ab = (int)(m0 / M_TOT);
    const int aa = ab >> 1, bb = ab & 1;
    const int pix0 = (int)(m0 - (long)ab * M_TOT);

    uint32_t adst[2]; const __half* asrc[2];
#pragma unroll
    for (int s = 0; s < 2; ++s) {
        int id  = t + s * 256;
        int row = id >> 2;
        int cq  = id & 3;
        asrc[s] = z + (m0 + row) * 256 + cq * 8;
        adst[s] = sb + row * 80 + cq * 16;
    }

    float c[10][4];
#pragma unroll
    for (int j = 0; j < 10; ++j)
#pragma unroll
        for (int q = 0; q < 4; ++q) c[j][q] = 0.f;

    auto load_tile = [&](int kt, int p) {
#pragma unroll
        for (int s = 0; s < 2; ++s)
            cp16(adst[s] + p * HSTAGE, asrc[s] + kt * 32, 16u);
        for (int ch = t; ch < 320; ch += 256) {
            int row = ch >> 2, cq = ch & 3;
            cp16(sb + 2 * HSTAGE + p * MB_STAGE + row * 80 + cq * 16,
                 wmTh + row * 256 + kt * 32 + cq * 8, 16u);
        }
        asm volatile("cp.async.commit_group;" ::: "memory");
    };

    const int lr = (lane & 7) + ((lane >> 3) & 1) * 8;
    const int lk = (lane >> 4) * 8;

    load_tile(0, 0);

    for (int kt = 0; kt < 8; ++kt) {
        const int p = kt & 1;
        if (kt < 7) {
            load_tile(kt + 1, p ^ 1);
            asm volatile("cp.async.wait_group 1;" ::: "memory");
        } else {
            asm volatile("cp.async.wait_group 0;" ::: "memory");
        }
        __syncthreads();

        const uint32_t Ab = sb + p * HSTAGE;
        const uint32_t Bb = sb + 2 * HSTAGE + p * MB_STAGE;
#pragma unroll
        for (int ks = 0; ks < 2; ++ks) {
            const int kc = ks * 16 + lk;
            uint32_t a[4];
            LDSM4(a[0], a[1], a[2], a[3], Ab + (wid * 16 + lr) * 80 + kc * 2);
            uint32_t bq[5][4];
#pragma unroll
            for (int j2 = 0; j2 < 5; ++j2)
                LDSM4(bq[j2][0], bq[j2][1], bq[j2][2], bq[j2][3],
                      Bb + (j2 * 16 + lr) * 80 + kc * 2);
#pragma unroll
            for (int j = 0; j < 10; ++j) {
                const int j2 = j >> 1, hi = j & 1;
                mma_f16(c[j], a, bq[j2][hi], bq[j2][hi + 2]);
            }
        }
        __syncthreads();
    }

    float bmv[10][2];
#pragma unroll
    for (int j = 0; j < 10; ++j) {
        int col = j * 8 + (lane & 3) * 2;
        bmv[j][0] = bm[col]; bmv[j][1] = bm[col + 1];
    }

    int pixA = pix0 + wid * 16 + (lane >> 2);
    int pixB = pixA + 8;
    int nA = pixA / 196, pA = pixA - nA * 196, iiA = pA / 14, jjA = pA - iiA * 14;
    int nB = pixB / 196, pB = pixB - nB * 196, iiB = pB / 14, jjB = pB - iiB * 14;
    float* opA = out + ((long)(nA * 28 + iiA * 2 + aa) * 28 + jjA * 2 + bb) * 80;
    float* opB = out + ((long)(nB * 28 + iiB * 2 + aa) * 28 + jjB * 2 + bb) * 80;

#pragma unroll
    for (int j = 0; j < 10; ++j) {
        int col = j * 8 + (lane & 3) * 2;
        *(float2*)&opA[col] = make_float2(c[j][0] + bmv[j][0], c[j][1] + bmv[j][1]);
        *(float2*)&opB[col] = make_float2(c[j][2] + bmv[j][0], c[j][3] + bmv[j][1]);
    }
}

// ---------------------------------------------------------------------------
extern "C" void kernel_launch(void* const* d_in, const int* in_sizes, int n_in,
                              void* d_out, int out_size)
{
    const float* x  = (const float*)d_in[0];
    const float* Wc = (const float*)d_in[1];
    const float* bc = (const float*)d_in[2];
    const float* Wt = (const float*)d_in[3];
    const float* bt = (const float*)d_in[4];
    const float* Wm = (const float*)d_in[5];
    const float* bm = (const float*)d_in[6];
    float* out = (float*)d_out;

    __half *h0, *h1, *wTh, *wdTh, *wmTh, *zh;
    cudaGetSymbolAddress((void**)&h0,   g_h0);
    cudaGetSymbolAddress((void**)&h1,   g_h1);
    cudaGetSymbolAddress((void**)&wTh,  g_wTh);
    cudaGetSymbolAddress((void**)&wdTh, g_wdTh);
    cudaGetSymbolAddress((void**)&wmTh, g_wmTh);
    cudaGetSymbolAddress((void**)&zh,   g_zh);

    cudaFuncSetAttribute(conv3x3_fp16,
                         cudaFuncAttributeMaxDynamicSharedMemorySize, SMEM_CONVH);
    cudaFuncSetAttribute(deconv_fp16,
                         cudaFuncAttributeMaxDynamicSharedMemorySize, SMEM_CONVH);
    cudaFuncSetAttribute(mask_fp16,
                         cudaFuncAttributeMaxDynamicSharedMemorySize, SMEM_MASK);

    // prep: fp16 conversion + weight transposes
    f2h_fp16<<<25088, 256>>>(x, h0);
    transpose_w_fp16<<<dim3(64, 9, 4), 256>>>(Wc, wTh);
    transpose_wd_fp16<<<dim3(64, 1, 4), 256>>>(Wt, wdTh);
    transpose_wm_fp16<<<80, 256>>>(Wm, wmTh);

    // conv chain (fp16)
    dim3 cgrid(1568, 2);
    conv3x3_fp16<<<cgrid, 256, SMEM_CONVH>>>(h0, wTh + 0L * WLSTRIDE, bc + 0,   h1);
    conv3x3_fp16<<<cgrid, 256, SMEM_CONVH>>>(h1, wTh + 1L * WLSTRIDE, bc + 256, h0);
    conv3x3_fp16<<<cgrid, 256, SMEM_CONVH>>>(h0, wTh + 2L * WLSTRIDE, bc + 512, h1);
    conv3x3_fp16<<<cgrid, 256, SMEM_CONVH>>>(h1, wTh + 3L * WLSTRIDE, bc + 768, h0);

    // deconv (per parity) + mask
    deconv_fp16<<<dim3(1568, 2, 4), 256, SMEM_CONVH>>>(h0, wdTh, bt, zh);
    mask_fp16<<<4 * M_TOT / 128, 256, SMEM_MASK>>>(zh, wmTh, bm, out);
}

// round 12
// speedup vs baseline: 1.8298x; 1.0280x over previous
// ROIMaskHead fp16 tensor-core pipeline, v4: conv mainloop -> 4-stage cp.async,
// single __syncthreads per iteration, L2-pair grid swizzle.
#include <cuda_runtime.h>
#include <cuda_fp16.h>
#include <cstdint>

#define NROI 1024
#define M_TOT (NROI * 196)          // 200704
#define KTOT  2304
#define WLSTRIDE (256 * KTOT)

// Device-global scratch (allocation-free per harness rules)
__device__ __half g_h0[M_TOT * 256];
__device__ __half g_h1[M_TOT * 256];
__device__ __half g_wTh[4 * 256 * KTOT];     // conv W [layer][co][k]
__device__ __half g_wdTh[4 * 256 * 256];     // deconv W [parity][co][ci]
__device__ __half g_wmTh[80 * 256];          // mask W [cls][ci]
__device__ __half g_zh[4L * M_TOT * 256];    // deconv out, parity-major

// ---------------------------------------------------------------------------
__device__ __forceinline__ uint32_t smem_u32(const void* p) {
    uint32_t a;
    asm("{ .reg .u64 t; cvta.to.shared.u64 t, %1; cvt.u32.u64 %0, t; }"
        : "=r"(a) : "l"(p));
    return a;
}
__device__ __forceinline__ void cp16(uint32_t dst, const void* src, uint32_t bytes) {
    asm volatile("cp.async.cg.shared.global [%0], [%1], 16, %2;"
                 :: "r"(dst), "l"(src), "r"(bytes) : "memory");
}
#define LDSM4(r0, r1, r2, r3, addr) \
    asm volatile("ldmatrix.sync.aligned.m8n8.x4.shared.b16 {%0,%1,%2,%3}, [%4];" \
                 : "=r"(r0), "=r"(r1), "=r"(r2), "=r"(r3) : "r"(addr))

__device__ __forceinline__ void mma_f16(float c[4], const uint32_t a[4],
                                        uint32_t b0, uint32_t b1) {
    asm volatile(
        "mma.sync.aligned.m16n8k16.row.col.f32.f16.f16.f32 "
        "{%0,%1,%2,%3}, {%4,%5,%6,%7}, {%8,%9}, {%0,%1,%2,%3};"
        : "+f"(c[0]), "+f"(c[1]), "+f"(c[2]), "+f"(c[3])
        : "r"(a[0]), "r"(a[1]), "r"(a[2]), "r"(a[3]), "r"(b0), "r"(b1));
}

// ---------------------------------------------------------------------------
// Prep kernels
// ---------------------------------------------------------------------------
__global__ __launch_bounds__(256)
void f2h_fp16(const float* __restrict__ in, __half* __restrict__ out)
{
    long i = (long)(blockIdx.x * 256 + threadIdx.x) * 8;
    float4 v0 = *(const float4*)(in + i);
    float4 v1 = *(const float4*)(in + i + 4);
    __half2 h[4];
    h[0] = __floats2half2_rn(v0.x, v0.y);
    h[1] = __floats2half2_rn(v0.z, v0.w);
    h[2] = __floats2half2_rn(v1.x, v1.y);
    h[3] = __floats2half2_rn(v1.z, v1.w);
    *(uint4*)(out + i) = *(uint4*)h;
}

__global__ __launch_bounds__(256)
void transpose_w_fp16(const float* __restrict__ Wc, __half* __restrict__ wTh)
{
    __shared__ float ts[32][33];
    const int l  = blockIdx.z;
    const int kq = blockIdx.y;
    const int ci0 = (blockIdx.x >> 3) * 32;
    const int co0 = (blockIdx.x & 7) * 32;
    const int tx = threadIdx.x & 31, ty = threadIdx.x >> 5;
#pragma unroll
    for (int i = ty; i < 32; i += 8)
        ts[i][tx] = Wc[((l * 9 + kq) * 256 + ci0 + i) * 256 + co0 + tx];
    __syncthreads();
#pragma unroll
    for (int i = ty; i < 32; i += 8)
        wTh[(long)(l * 256 + co0 + i) * KTOT + kq * 256 + ci0 + tx] =
            __float2half_rn(ts[tx][i]);
}

__global__ __launch_bounds__(256)
void transpose_wd_fp16(const float* __restrict__ Wt, __half* __restrict__ wdTh)
{
    __shared__ float ts[32][33];
    const int ab  = blockIdx.z;
    const int ci0 = (blockIdx.x >> 3) * 32;
    const int co0 = (blockIdx.x & 7) * 32;
    const int tx = threadIdx.x & 31, ty = threadIdx.x >> 5;
    const float* src = Wt + (3 - ab) * 65536;   // Wt[1-a][1-b] (proven in R1)
#pragma unroll
    for (int i = ty; i < 32; i += 8)
        ts[i][tx] = src[(ci0 + i) * 256 + co0 + tx];
    __syncthreads();
#pragma unroll
    for (int i = ty; i < 32; i += 8)
        wdTh[ab * 65536 + (co0 + i) * 256 + ci0 + tx] = __float2half_rn(ts[tx][i]);
}

__global__ __launch_bounds__(256)
void transpose_wm_fp16(const float* __restrict__ Wm, __half* __restrict__ wmTh)
{
    int i = blockIdx.x * 256 + threadIdx.x;
    if (i < 80 * 256) {
        int cls = i >> 8, ci = i & 255;
        wmTh[i] = __float2half_rn(Wm[ci * 80 + cls]);
    }
}

// ---------------------------------------------------------------------------
// Conv 3x3 SAME (256->256) + bias + ReLU, fp16 mma.m16n8k16.
// BM=128 BN=128 BK=32, 256 thr, 8 warps (2M x 4N), warp tile 64x32.
// v4: 4-stage cp.async pipeline, ONE __syncthreads per kt iteration.
// Grid linearized: bid pairs (2m, 2m+1) share the A tile and run adjacent.
// ---------------------------------------------------------------------------
#define HSTAGE (128 * 40 * 2)                // 10240 B per tile (A or B)
#define NSTAGE 4
#define STG_BYTES (2 * HSTAGE)               // A+B per stage = 20480
#define SMEM_CONVH (NSTAGE * STG_BYTES + 1024)   // 82944 B

__global__ __launch_bounds__(256, 2)
void conv3x3_fp16(const __half* __restrict__ in,
                  const __half* __restrict__ wTh,
                  const float* __restrict__ bias,
                  __half* __restrict__ out)
{
    extern __shared__ char smem[];
    const uint32_t sb = smem_u32(smem);
    float* bias_s = (float*)(smem + NSTAGE * STG_BYTES);

    const int t = threadIdx.x, wid = t >> 5, lane = t & 31;
    const int bid = blockIdx.x;
    const int m0 = (bid >> 1) * 128;        // pair-adjacent CTAs share A
    const int n0 = (bid & 1) * 128;
    const int warpM = (wid & 1) * 64;
    const int warpN = (wid >> 1) * 32;

    if (t < 32) ((float4*)bias_s)[t] = ((const float4*)(bias + n0))[t];

    // load mapping: 2 A + 2 B 16B-chunks per thread (row=64B -> 4 chunks)
    int ahh[2], aww[2]; long abase[2];
    uint32_t adst[2], bdst[2];
    const __half* bsrc[2];
#pragma unroll
    for (int s = 0; s < 2; ++s) {
        int id  = t + s * 256;
        int row = id >> 2;
        int cq  = id & 3;
        int m = m0 + row;
        int n = m / 196;
        int pp = m - n * 196;
        int hh = pp / 14;
        ahh[s] = hh; aww[s] = pp - hh * 14;
        abase[s] = (long)n * 50176 + cq * 8;
        adst[s] = sb + row * 80 + cq * 16;
        bsrc[s] = wTh + (long)(n0 + row) * KTOT + cq * 8;
        bdst[s] = sb + HSTAGE + row * 80 + cq * 16;
    }

    float c[4][4][4];
#pragma unroll
    for (int i = 0; i < 4; ++i)
#pragma unroll
        for (int j = 0; j < 4; ++j)
#pragma unroll
            for (int q = 0; q < 4; ++q) c[i][j][q] = 0.f;

    auto load_tile = [&](int kt, int p) {
        const int kq = kt >> 3, ci0 = (kt & 7) << 5;
        const int kh = kq / 3, kw = kq - kh * 3;
        const uint32_t off = p * STG_BYTES;
#pragma unroll
        for (int s = 0; s < 2; ++s) {
            int ih = ahh[s] + kh - 1, iw = aww[s] + kw - 1;
            bool ok = ((unsigned)ih < 14u) & ((unsigned)iw < 14u);
            int ihc = ok ? ih : 0, iwc = ok ? iw : 0;
            cp16(adst[s] + off, in + abase[s] + (ihc * 14 + iwc) * 256 + ci0,
                 ok ? 16u : 0u);
        }
#pragma unroll
        for (int s = 0; s < 2; ++s)
            cp16(bdst[s] + off, bsrc[s] + kt * 32, 16u);
        asm volatile("cp.async.commit_group;" ::: "memory");
    };

    // ldmatrix lane addressing
    const int lr = (lane & 7) + ((lane >> 3) & 1) * 8;   // row within 16
    const int lk = (lane >> 4) * 8;                      // k col 0/8

    // prologue: fill NSTAGE-1 stages
    load_tile(0, 0);
    load_tile(1, 1);
    load_tile(2, 2);

    for (int kt = 0; kt < 72; ++kt) {
        const int p = kt & (NSTAGE - 1);
        asm volatile("cp.async.wait_group %0;" :: "n"(NSTAGE - 2) : "memory");
        __syncthreads();

        const uint32_t Ab = sb + p * STG_BYTES;
        const uint32_t Bb = Ab + HSTAGE;
#pragma unroll
        for (int ks = 0; ks < 2; ++ks) {
            const int kc = ks * 16 + lk;
            uint32_t a[4][4], bq[2][4];
#pragma unroll
            for (int i = 0; i < 4; ++i)
                LDSM4(a[i][0], a[i][1], a[i][2], a[i][3],
                      Ab + (warpM + i * 16 + lr) * 80 + kc * 2);
#pragma unroll
            for (int j2 = 0; j2 < 2; ++j2)
                LDSM4(bq[j2][0], bq[j2][1], bq[j2][2], bq[j2][3],
                      Bb + (warpN + j2 * 16 + lr) * 80 + kc * 2);
#pragma unroll
            for (int i = 0; i < 4; ++i)
#pragma unroll
                for (int j = 0; j < 4; ++j) {
                    const int j2 = j >> 1, hi = j & 1;
                    mma_f16(c[i][j], a[i], bq[j2][hi], bq[j2][hi + 2]);
                }
        }
        // tail load writes stage (kt+3)%4 == (kt-1)%4: all warps finished
        // computing it before the sync above -> no second barrier needed.
        if (kt + NSTAGE - 1 < 72)
            load_tile(kt + NSTAGE - 1, (kt + NSTAGE - 1) & (NSTAGE - 1));
    }

    // epilogue: bias + relu -> half2
#pragma unroll
    for (int j = 0; j < 4; ++j) {
        const int col = warpN + j * 8 + (lane & 3) * 2;
        const float b0 = bias_s[col], b1 = bias_s[col + 1];
#pragma unroll
        for (int i = 0; i < 4; ++i) {
            long r0 = m0 + warpM + i * 16 + (lane >> 2);
            __half2 h0 = __floats2half2_rn(fmaxf(c[i][j][0] + b0, 0.f),
                                           fmaxf(c[i][j][1] + b1, 0.f));
            __half2 h1 = __floats2half2_rn(fmaxf(c[i][j][2] + b0, 0.f),
                                           fmaxf(c[i][j][3] + b1, 0.f));
            *(__half2*)&out[(r0 << 8) + n0 + col]       = h0;
            *(__half2*)&out[((r0 + 8) << 8) + n0 + col] = h1;
        }
    }
}

// ---------------------------------------------------------------------------
// D1: deconv GEMM per parity, fp16 (unchanged from R11 pass; 2-stage)
// ---------------------------------------------------------------------------
#define SMEM_DCONV (4 * HSTAGE + 1024)

__global__ __launch_bounds__(256, 2)
void deconv_fp16(const __half* __restrict__ y,
                 const __half* __restrict__ wdTh,
                 const float* __restrict__ bt,
                 __half* __restrict__ z)
{
    extern __shared__ char smem[];
    const uint32_t sb = smem_u32(smem);
    float* bias_s = (float*)(smem + 4 * HSTAGE);

    const int t = threadIdx.x, wid = t >> 5, lane = t & 31;
    const int m0 = blockIdx.x * 128;
    const int n0 = blockIdx.y * 128;
    const int ab = blockIdx.z;
    const int warpM = (wid & 1) * 64;
    const int warpN = (wid >> 1) * 32;

    if (t < 32) ((float4*)bias_s)[t] = ((const float4*)(bt + n0))[t];

    uint32_t adst[2], bdst[2];
    const __half* asrc[2];
    const __half* bsrc[2];
#pragma unroll
    for (int s = 0; s < 2; ++s) {
        int id  = t + s * 256;
        int row = id >> 2;
        int cq  = id & 3;
        asrc[s] = y + (long)(m0 + row) * 256 + cq * 8;
        adst[s] = sb + row * 80 + cq * 16;
        bsrc[s] = wdTh + ab * 65536 + (n0 + row) * 256 + cq * 8;
        bdst[s] = sb + 2 * HSTAGE + row * 80 + cq * 16;
    }

    float c[4][4][4];
#pragma unroll
    for (int i = 0; i < 4; ++i)
#pragma unroll
        for (int j = 0; j < 4; ++j)
#pragma unroll
            for (int q = 0; q < 4; ++q) c[i][j][q] = 0.f;

    auto load_tile = [&](int kt, int p) {
#pragma unroll
        for (int s = 0; s < 2; ++s) cp16(adst[s] + p * HSTAGE, asrc[s] + kt * 32, 16u);
#pragma unroll
        for (int s = 0; s < 2; ++s) cp16(bdst[s] + p * HSTAGE, bsrc[s] + kt * 32, 16u);
        asm volatile("cp.async.commit_group;" ::: "memory");
    };

    const int lr = (lane & 7) + ((lane >> 3) & 1) * 8;
    const int lk = (lane >> 4) * 8;

    load_tile(0, 0);

    for (int kt = 0; kt < 8; ++kt) {
        const int p = kt & 1;
        if (kt < 7) {
            load_tile(kt + 1, p ^ 1);
            asm volatile("cp.async.wait_group 1;" ::: "memory");
        } else {
            asm volatile("cp.async.wait_group 0;" ::: "memory");
        }
        __syncthreads();

        const uint32_t Ab = sb + p * HSTAGE;
        const uint32_t Bb = sb + 2 * HSTAGE + p * HSTAGE;
#pragma unroll
        for (int ks = 0; ks < 2; ++ks) {
            const int kc = ks * 16 + lk;
            uint32_t a[4][4], bq[2][4];
#pragma unroll
            for (int i = 0; i < 4; ++i)
                LDSM4(a[i][0], a[i][1], a[i][2], a[i][3],
                      Ab + (warpM + i * 16 + lr) * 80 + kc * 2);
#pragma unroll
            for (int j2 = 0; j2 < 2; ++j2)
                LDSM4(bq[j2][0], bq[j2][1], bq[j2][2], bq[j2][3],
                      Bb + (warpN + j2 * 16 + lr) * 80 + kc * 2);
#pragma unroll
            for (int i = 0; i < 4; ++i)
#pragma unroll
                for (int j = 0; j < 4; ++j) {
                    const int j2 = j >> 1, hi = j & 1;
                    mma_f16(c[i][j], a[i], bq[j2][hi], bq[j2][hi + 2]);
                }
        }
        __syncthreads();
    }

    __half* zout = z + (long)ab * M_TOT * 256;
#pragma unroll
    for (int j = 0; j < 4; ++j) {
        const int col = warpN + j * 8 + (lane & 3) * 2;
        const float b0 = bias_s[col], b1 = bias_s[col + 1];
#pragma unroll
        for (int i = 0; i < 4; ++i) {
            long r0 = m0 + warpM + i * 16 + (lane >> 2);
            __half2 h0 = __floats2half2_rn(fmaxf(c[i][j][0] + b0, 0.f),
                                           fmaxf(c[i][j][1] + b1, 0.f));
            __half2 h1 = __floats2half2_rn(fmaxf(c[i][j][2] + b0, 0.f),
                                           fmaxf(c[i][j][3] + b1, 0.f));
            *(__half2*)&zout[(r0 << 8) + n0 + col]       = h0;
            *(__half2*)&zout[((r0 + 8) << 8) + n0 + col] = h1;
        }
    }
}

// ---------------------------------------------------------------------------
// D2: mask GEMM fp16 (unchanged from R11 pass)
// ---------------------------------------------------------------------------
#define MB_STAGE (80 * 40 * 2)                   // 6400 B
#define SMEM_MASK (2 * HSTAGE + 2 * MB_STAGE)    // 33280 B

__global__ __launch_bounds__(256, 2)
void mask_fp16(const __half* __restrict__ z,
               const __half* __restrict__ wmTh,
               const float* __restrict__ bm,
               float* __restrict__ out)
{
    extern __shared__ char smem[];
    const uint32_t sb = smem_u32(smem);
    const int t = threadIdx.x, wid = t >> 5, lane = t & 31;
    const long m0 = (long)blockIdx.x * 128;
    const int ab = (int)(m0 / M_TOT);
    const int aa = ab >> 1, bb = ab & 1;
    const int pix0 = (int)(m0 - (long)ab * M_TOT);

    uint32_t adst[2]; const __half* asrc[2];
#pragma unroll
    for (int s = 0; s < 2; ++s) {
        int id  = t + s * 256;
        int row = id >> 2;
        int cq  = id & 3;
        asrc[s] = z + (m0 + row) * 256 + cq * 8;
        adst[s] = sb + row * 80 + cq * 16;
    }

    float c[10][4];
#pragma unroll
    for (int j = 0; j < 10; ++j)
#pragma unroll
        for (int q = 0; q < 4; ++q) c[j][q] = 0.f;

    auto load_tile = [&](int kt, int p) {
#pragma unroll
        for (int s = 0; s < 2; ++s)
            cp16(adst[s] + p * HSTAGE, asrc[s] + kt * 32, 16u);
        for (int ch = t; ch < 320; ch += 256) {
            int row = ch >> 2, cq = ch & 3;
            cp16(sb + 2 * HSTAGE + p * MB_STAGE + row * 80 + cq * 16,
                 wmTh + row * 256 + kt * 32 + cq * 8, 16u);
        }
        asm volatile("cp.async.commit_group;" ::: "memory");
    };

    const int lr = (lane & 7) + ((lane >> 3) & 1) * 8;
    const int lk = (lane >> 4) * 8;

    load_tile(0, 0);

    for (int kt = 0; kt < 8; ++kt) {
        const int p = kt & 1;
        if (kt < 7) {
            load_tile(kt + 1, p ^ 1);
            asm volatile("cp.async.wait_group 1;" ::: "memory");
        } else {
            asm volatile("cp.async.wait_group 0;" ::: "memory");
        }
        __syncthreads();

        const uint32_t Ab = sb + p * HSTAGE;
        const uint32_t Bb = sb + 2 * HSTAGE + p * MB_STAGE;
#pragma unroll
        for (int ks = 0; ks < 2; ++ks) {
            const int kc = ks * 16 + lk;
            uint32_t a[4];
            LDSM4(a[0], a[1], a[2], a[3], Ab + (wid * 16 + lr) * 80 + kc * 2);
            uint32_t bq[5][4];
#pragma unroll
            for (int j2 = 0; j2 < 5; ++j2)
                LDSM4(bq[j2][0], bq[j2][1], bq[j2][2], bq[j2][3],
                      Bb + (j2 * 16 + lr) * 80 + kc * 2);
#pragma unroll
            for (int j = 0; j < 10; ++j) {
                const int j2 = j >> 1, hi = j & 1;
                mma_f16(c[j], a, bq[j2][hi], bq[j2][hi + 2]);
            }
        }
        __syncthreads();
    }

    float bmv[10][2];
#pragma unroll
    for (int j = 0; j < 10; ++j) {
        int col = j * 8 + (lane & 3) * 2;
        bmv[j][0] = bm[col]; bmv[j][1] = bm[col + 1];
    }

    int pixA = pix0 + wid * 16 + (lane >> 2);
    int pixB = pixA + 8;
    int nA = pixA / 196, pA = pixA - nA * 196, iiA = pA / 14, jjA = pA - iiA * 14;
    int nB = pixB / 196, pB = pixB - nB * 196, iiB = pB / 14, jjB = pB - iiB * 14;
    float* opA = out + ((long)(nA * 28 + iiA * 2 + aa) * 28 + jjA * 2 + bb) * 80;
    float* opB = out + ((long)(nB * 28 + iiB * 2 + aa) * 28 + jjB * 2 + bb) * 80;

#pragma unroll
    for (int j = 0; j < 10; ++j) {
        int col = j * 8 + (lane & 3) * 2;
        *(float2*)&opA[col] = make_float2(c[j][0] + bmv[j][0], c[j][1] + bmv[j][1]);
        *(float2*)&opB[col] = make_float2(c[j][2] + bmv[j][0], c[j][3] + bmv[j][1]);
    }
}

// ---------------------------------------------------------------------------
extern "C" void kernel_launch(void* const* d_in, const int* in_sizes, int n_in,
                              void* d_out, int out_size)
{
    const float* x  = (const float*)d_in[0];
    const float* Wc = (const float*)d_in[1];
    const float* bc = (const float*)d_in[2];
    const float* Wt = (const float*)d_in[3];
    const float* bt = (const float*)d_in[4];
    const float* Wm = (const float*)d_in[5];
    const float* bm = (const float*)d_in[6];
    float* out = (float*)d_out;

    __half *h0, *h1, *wTh, *wdTh, *wmTh, *zh;
    cudaGetSymbolAddress((void**)&h0,   g_h0);
    cudaGetSymbolAddress((void**)&h1,   g_h1);
    cudaGetSymbolAddress((void**)&wTh,  g_wTh);
    cudaGetSymbolAddress((void**)&wdTh, g_wdTh);
    cudaGetSymbolAddress((void**)&wmTh, g_wmTh);
    cudaGetSymbolAddress((void**)&zh,   g_zh);

    cudaFuncSetAttribute(conv3x3_fp16,
                         cudaFuncAttributeMaxDynamicSharedMemorySize, SMEM_CONVH);
    cudaFuncSetAttribute(deconv_fp16,
                         cudaFuncAttributeMaxDynamicSharedMemorySize, SMEM_DCONV);
    cudaFuncSetAttribute(mask_fp16,
                         cudaFuncAttributeMaxDynamicSharedMemorySize, SMEM_MASK);

    // prep: fp16 conversion + weight transposes
    f2h_fp16<<<25088, 256>>>(x, h0);
    transpose_w_fp16<<<dim3(64, 9, 4), 256>>>(Wc, wTh);
    transpose_wd_fp16<<<dim3(64, 1, 4), 256>>>(Wt, wdTh);
    transpose_wm_fp16<<<80, 256>>>(Wm, wmTh);

    // conv chain (fp16, linearized pair-swizzled grid)
    conv3x3_fp16<<<3136, 256, SMEM_CONVH>>>(h0, wTh + 0L * WLSTRIDE, bc + 0,   h1);
    conv3x3_fp16<<<3136, 256, SMEM_CONVH>>>(h1, wTh + 1L * WLSTRIDE, bc + 256, h0);
    conv3x3_fp16<<<3136, 256, SMEM_CONVH>>>(h0, wTh + 2L * WLSTRIDE, bc + 512, h1);
    conv3x3_fp16<<<3136, 256, SMEM_CONVH>>>(h1, wTh + 3L * WLSTRIDE, bc + 768, h0);

    // deconv (per parity) + mask
    deconv_fp16<<<dim3(1568, 2, 4), 256, SMEM_DCONV>>>(h0, wdTh, bt, zh);
    mask_fp16<<<4 * M_TOT / 128, 256, SMEM_MASK>>>(zh, wmTh, bm, out);
}